// round 6
// baseline (speedup 1.0000x reference)
#include <cuda_runtime.h>
#include <cstdint>

#define LOCN  10000
#define DLOC  128
#define DST   64
#define DSUM  256
#define BB    64
#define SS    128
#define NROWS_MAX (BB * SS)   // max unique rows = 8192

// Scratch: Y = relu(A @ W_loc + b)*16 for needed rows (5.12 MB).
__device__ float g_Y[(size_t)LOCN * DLOC];
__device__ int   g_flag[LOCN];     // epoch-tagged marks (never cleared)
__device__ int   g_list[NROWS_MAX];
__device__ int   g_count;          // unique rows this launch
__device__ int   g_work;           // work-stealing cursor
__device__ int   g_epoch;          // bumped by gather kernel each launch

// ---------------------------------------------------------------------------
// Kernel 1: mark + compact, multi-block, warp-aggregated.
// Epoch trick: row is marked iff g_flag[r] == e, where e = g_epoch + 1.
// One spread atomicExch per thread, ONE atomicAdd per warp.
// g_count/g_work were reset by the previous launch's gather kernel
// (and are zero-initialized for the very first call).
// ---------------------------------------------------------------------------
__global__ void __launch_bounds__(512) mark_compact_kernel(
    const int* __restrict__ loc)
{
    const int i = blockIdx.x * blockDim.x + threadIdx.x;   // 0..8191
    const int lane = threadIdx.x & 31;
    const int e = g_epoch + 1;                              // this launch's epoch

    const int r = loc[i];
    const int old = atomicExch(&g_flag[r], e);
    const bool first = (old != e);

    const unsigned mask = __ballot_sync(0xffffffffu, first);
    int base = 0;
    if (lane == 0 && mask) base = atomicAdd(&g_count, __popc(mask));
    base = __shfl_sync(0xffffffffu, base, 0);
    if (first) {
        const int pos = base + __popc(mask & ((1u << lane) - 1u));
        g_list[pos] = r;
    }
}

// ---------------------------------------------------------------------------
// Kernel 2: Y = relu(A@W + b)*16. Persistent warps pop rows from g_work.
// Per row: 8 float4/lane/iter with next-iter prefetch => up to 16 loads
// in flight per lane.
// ---------------------------------------------------------------------------
__global__ void __launch_bounds__(256, 2) spmm_rows_kernel(
    const float* __restrict__ A, const float* __restrict__ W,
    const float* __restrict__ bias)
{
    const int lane  = threadIdx.x & 31;
    const int count = g_count;

    constexpr int NV4   = LOCN / 4;                    // 2500
    constexpr int K     = 8;                           // float4 per lane per iter
    constexpr int VPI   = 32 * K;                      // 256 float4/warp/iter
    constexpr int NITER = (NV4 + VPI - 1) / VPI;       // 10
    const float4 Z = make_float4(0.f, 0.f, 0.f, 0.f);

    const float b0v = bias[lane];
    const float b1v = bias[lane + 32];
    const float b2v = bias[lane + 64];
    const float b3v = bias[lane + 96];

    for (;;) {
        int widx = 0;
        if (lane == 0) widx = atomicAdd(&g_work, 1);
        widx = __shfl_sync(0xffffffffu, widx, 0);
        if (widx >= count) return;
        const int row_idx = g_list[widx];

        const float4* __restrict__ row =
            reinterpret_cast<const float4*>(A + (size_t)row_idx * LOCN);

        float acc0 = 0.f, acc1 = 0.f, acc2 = 0.f, acc3 = 0.f;

        float4 cur[K], nxt[K];
        #pragma unroll
        for (int k = 0; k < K; ++k) {
            const int idx = lane + 32 * k;
            cur[k] = (idx < NV4) ? __ldcs(&row[idx]) : Z;
        }

        for (int it = 0; it < NITER; ++it) {
            if (it + 1 < NITER) {
                const int nbase = (it + 1) * VPI + lane;
                #pragma unroll
                for (int k = 0; k < K; ++k) {
                    const int idx = nbase + 32 * k;
                    nxt[k] = (idx < NV4) ? __ldcs(&row[idx]) : Z;
                }
            }

            #pragma unroll
            for (int k = 0; k < K; ++k) {
                const float4 v = cur[k];
                const bool nz = (v.x != 0.f) | (v.y != 0.f) |
                                (v.z != 0.f) | (v.w != 0.f);
                unsigned m = __ballot_sync(0xffffffffu, nz);
                while (m) {
                    const int j = __ffs(m) - 1;
                    m &= m - 1;
                    const float vx = __shfl_sync(0xffffffffu, v.x, j);
                    const float vy = __shfl_sync(0xffffffffu, v.y, j);
                    const float vz = __shfl_sync(0xffffffffu, v.z, j);
                    const float vw = __shfl_sync(0xffffffffu, v.w, j);
                    const int n0 = (it * VPI + k * 32 + j) * 4;

                    const float* __restrict__ Wr = W + (size_t)n0 * DLOC + lane;
                    if (vx != 0.f) {
                        acc0 = fmaf(vx, Wr[0],  acc0);
                        acc1 = fmaf(vx, Wr[32], acc1);
                        acc2 = fmaf(vx, Wr[64], acc2);
                        acc3 = fmaf(vx, Wr[96], acc3);
                    }
                    Wr += DLOC;
                    if (vy != 0.f) {
                        acc0 = fmaf(vy, Wr[0],  acc0);
                        acc1 = fmaf(vy, Wr[32], acc1);
                        acc2 = fmaf(vy, Wr[64], acc2);
                        acc3 = fmaf(vy, Wr[96], acc3);
                    }
                    Wr += DLOC;
                    if (vz != 0.f) {
                        acc0 = fmaf(vz, Wr[0],  acc0);
                        acc1 = fmaf(vz, Wr[32], acc1);
                        acc2 = fmaf(vz, Wr[64], acc2);
                        acc3 = fmaf(vz, Wr[96], acc3);
                    }
                    Wr += DLOC;
                    if (vw != 0.f) {
                        acc0 = fmaf(vw, Wr[0],  acc0);
                        acc1 = fmaf(vw, Wr[32], acc1);
                        acc2 = fmaf(vw, Wr[64], acc2);
                        acc3 = fmaf(vw, Wr[96], acc3);
                    }
                }
            }

            #pragma unroll
            for (int k = 0; k < K; ++k) cur[k] = nxt[k];
        }

        const float s = 16.0f;
        float* __restrict__ y = g_Y + (size_t)row_idx * DLOC + lane;
        y[0]  = fmaxf(acc0 + b0v, 0.f) * s;
        y[32] = fmaxf(acc1 + b1v, 0.f) * s;
        y[64] = fmaxf(acc2 + b2v, 0.f) * s;
        y[96] = fmaxf(acc3 + b3v, 0.f) * s;
    }
}

// ---------------------------------------------------------------------------
// Kernel 3: assemble outputs (float4), 4 independent elements per thread.
// Epilogue: bump epoch + reset counters for the next launch/replay.
// ---------------------------------------------------------------------------
__global__ void __launch_bounds__(256) gather_concat_kernel(
    const int*   __restrict__ loc,
    const int*   __restrict__ st,
    const int*   __restrict__ ed,
    const float* __restrict__ emb_st,
    const float* __restrict__ emb_ed,
    float4*      __restrict__ out)
{
    constexpr int N1V  = BB * SS * DSUM / 4;           // 524288
    constexpr int NTV  = N1V + BB * SS * DST / 4;      // 655360
    constexpr int QTR  = NTV / 4;                      // 163840

    const int tid = blockIdx.x * blockDim.x + threadIdx.x;
    if (tid >= QTR) return;

    // Reset bookkeeping for next launch (graph-ordered before next mark).
    if (tid == 0) {
        g_epoch = g_epoch + 1;
        g_count = 0;
        g_work  = 0;
    }

    const float4* __restrict__ Yv  = reinterpret_cast<const float4*>(g_Y);
    const float4* __restrict__ stv = reinterpret_cast<const float4*>(emb_st);
    const float4* __restrict__ edv = reinterpret_cast<const float4*>(emb_ed);
    const float s = 16.0f;

    #pragma unroll
    for (int h = 0; h < 4; ++h) {
        const int idx = tid + h * QTR;
        float4 r;
        if (idx < N1V) {
            const int bs = idx >> 6;
            const int d4 = idx & 63;
            if (d4 < 32) {                               // loc (pre-scaled)
                r = Yv[(size_t)loc[bs] * 32 + d4];
            } else if (d4 < 48) {                        // st
                r = stv[st[bs] * 16 + (d4 - 32)];
                r.x *= s; r.y *= s; r.z *= s; r.w *= s;
            } else {                                     // ed
                r = edv[ed[bs] * 16 + (d4 - 48)];
                r.x *= s; r.y *= s; r.z *= s; r.w *= s;
            }
        } else {
            const int j  = idx - N1V;
            const int bs = j >> 4;
            const int d4 = j & 15;
            const int ss = bs & (SS - 1);
            const int yt = (ss < SS - 1) ? st[bs + 1] : 0;
            r = stv[yt * 16 + d4];                       // res_yt NOT scaled
        }
        out[idx] = r;
    }
}

extern "C" void kernel_launch(void* const* d_in, const int* in_sizes, int n_in,
                              void* d_out, int out_size)
{
    const int*   loc    = (const int*)  d_in[0];
    const int*   st     = (const int*)  d_in[1];
    const int*   ed     = (const int*)  d_in[2];
    const float* A      = (const float*)d_in[3];
    const float* W_loc  = (const float*)d_in[4];
    const float* b_loc  = (const float*)d_in[5];
    const float* emb_st = (const float*)d_in[6];
    const float* emb_ed = (const float*)d_in[7];

    // 8192 threads exactly; multi-block, warp-aggregated compaction.
    mark_compact_kernel<<<16, 512>>>(loc);

    // Persistent work-stealing: 2 blocks/SM x 148 SMs.
    spmm_rows_kernel<<<296, 256>>>(A, W_loc, b_loc);

    constexpr int qtr = (BB * SS * DSUM + BB * SS * DST) / 4 / 4;
    gather_concat_kernel<<<(qtr + 255) / 256, 256>>>(
        loc, st, ed, emb_st, emb_ed, (float4*)d_out);
}